// round 3
// baseline (speedup 1.0000x reference)
#include <cuda_runtime.h>
#include <cstdint>

// NF4 MLP: out = (silu(x@w1^T) * (x@w2^T)) @ w3^T
// w1,w2,w3 NF4-dequantized (blockwise absmax + double-quantized scalers).
#define DD 4096
#define HH 11008
#define TT 2048

__constant__ float c_nf4[16] = {
    -1.0f, -0.6961928009986877f, -0.5250730514526367f, -0.39491748809814453f,
    -0.28444138169288635f, -0.18477343022823334f, -0.09105003625154495f, 0.0f,
    0.07958029955625534f, 0.16093020141124725f, 0.24611230194568634f,
    0.33791524171829224f, 0.44070982933044434f, 0.5626170039176941f,
    0.7229568362236023f, 1.0f};

// Static scratch (device allocation is banned; __device__ globals are the
// sanctioned workaround). ~720 MB total.
__device__ float g_w1[(size_t)HH * DD];
__device__ float g_w2[(size_t)HH * DD];
__device__ float g_w3[(size_t)DD * HH];
__device__ float g_a[(size_t)TT * HH];   // silu input, then reused as h
__device__ float g_b[(size_t)TT * HH];

// dtype flags for (idx, qs) inputs: 0 = int8, 1 = int32 (widened), 2 = float32
__device__ int g_flags[2];

// ---------------------------------------------------------------------------
// Probe the raw byte pattern of idx / qs buffers to discover how the harness
// uploaded the reference's int8 arrays. idx codes are 0..15; qs are -127..127.
//   int32 widening: idx -> bytes 1..3 all zero; qs -> bytes 1..3 = sign ext.
//   float32      : low mantissa bytes (0..1) all zero for small integers.
//   int8 (native): byte stream of values; none of the above patterns hold.
// ---------------------------------------------------------------------------
__global__ void detect_types(const uint8_t* __restrict__ idx,
                             const uint8_t* __restrict__ qs) {
    if (threadIdx.x | blockIdx.x) return;
    // --- idx ---
    int nz0 = 0, nz1 = 0, nz23 = 0;
    for (int i = 0; i < 256; i++) {
        nz0  += (idx[i * 4 + 0] != 0);
        nz1  += (idx[i * 4 + 1] != 0);
        nz23 += (idx[i * 4 + 2] != 0) + (idx[i * 4 + 3] != 0);
    }
    int im;
    if (nz1 == 0 && nz23 == 0) im = 1;          // int32
    else if (nz0 == 0 && nz1 == 0) im = 2;      // float32
    else im = 0;                                 // int8
    g_flags[0] = im;

    // --- qs ---
    bool i32ok = true, f32ok = true;
    for (int i = 0; i < 256; i++) {
        uint8_t b0 = qs[i * 4], b1 = qs[i * 4 + 1],
                b2 = qs[i * 4 + 2], b3 = qs[i * 4 + 3];
        uint8_t ext = (b0 & 0x80) ? 0xFF : 0x00;
        if (!(b1 == ext && b2 == ext && b3 == ext)) i32ok = false;
        if (b0 != 0 || b1 != 0) f32ok = false;
    }
    g_flags[1] = i32ok ? 1 : (f32ok ? 2 : 0);
}

// ---------------------------------------------------------------------------
// Dequant: w[i] = NF4[idx[i]] * (qs[i/64]/qf[i/16384] + m)
// 4 elements/thread; 4 elems always share one 64-elem block.
// ---------------------------------------------------------------------------
__global__ void dequant_kernel(const void* __restrict__ idxv,
                               const void* __restrict__ qsv,
                               const float* __restrict__ qf,
                               const float* __restrict__ mp,
                               float* __restrict__ out, int n4) {
    int i = blockIdx.x * blockDim.x + threadIdx.x;
    if (i >= n4) return;
    const float m = *mp;
    const int im = g_flags[0], qm = g_flags[1];
    int blk = i >> 4;  // (i*4) >> 6 : 64-elem nf4 block index

    float q;
    if (qm == 1)      q = (float)((const int*)qsv)[blk];
    else if (qm == 2) q = ((const float*)qsv)[blk];
    else              q = (float)((const int8_t*)qsv)[blk];
    float scal = q / qf[blk >> 8] + m;

    int c0, c1, c2, c3;
    if (im == 1) {
        int4 w = ((const int4*)idxv)[i];
        c0 = w.x; c1 = w.y; c2 = w.z; c3 = w.w;
    } else if (im == 2) {
        float4 w = ((const float4*)idxv)[i];
        c0 = (int)w.x; c1 = (int)w.y; c2 = (int)w.z; c3 = (int)w.w;
    } else {
        char4 c = ((const char4*)idxv)[i];
        c0 = c.x; c1 = c.y; c2 = c.z; c3 = c.w;
    }
    float4 o;
    o.x = c_nf4[c0 & 15] * scal;
    o.y = c_nf4[c1 & 15] * scal;
    o.z = c_nf4[c2 & 15] * scal;
    o.w = c_nf4[c3 & 15] * scal;
    ((float4*)out)[i] = o;
}

// ---------------------------------------------------------------------------
// fp32 NT SGEMM: C[M,N] = A[M,K] (row-major) * B[N,K]^T (row-major)
// 128x128 block tile, BK=16, 256 threads, 8x8 register tile per thread,
// register-prefetch pipelining. M,N % 128 == 0, K % 16 == 0.
// ---------------------------------------------------------------------------
__global__ __launch_bounds__(256, 2) void sgemm_nt(const float* __restrict__ A,
                                                   const float* __restrict__ B,
                                                   float* __restrict__ C,
                                                   int M, int N, int K) {
    __shared__ float As[16][128];
    __shared__ float Bs[16][128];

    const int tid  = threadIdx.x;
    const int trow = tid >> 4;   // 0..15 (M dir)
    const int tcol = tid & 15;   // 0..15 (N dir)

    const float* Ab = A + (size_t)(blockIdx.y * 128) * K;
    const float* Bb = B + (size_t)(blockIdx.x * 128) * K;

    const int lr = tid >> 2;        // 0..63
    const int lc = (tid & 3) << 2;  // 0,4,8,12

    float acc[8][8] = {};
    float4 na[2], nb[2];

#pragma unroll
    for (int i = 0; i < 2; i++) {
        int r = lr + i * 64;
        na[i] = *(const float4*)(Ab + (size_t)r * K + lc);
        nb[i] = *(const float4*)(Bb + (size_t)r * K + lc);
    }

    for (int kt = 0; kt < K; kt += 16) {
#pragma unroll
        for (int i = 0; i < 2; i++) {
            int r = lr + i * 64;
            As[lc + 0][r] = na[i].x; As[lc + 1][r] = na[i].y;
            As[lc + 2][r] = na[i].z; As[lc + 3][r] = na[i].w;
            Bs[lc + 0][r] = nb[i].x; Bs[lc + 1][r] = nb[i].y;
            Bs[lc + 2][r] = nb[i].z; Bs[lc + 3][r] = nb[i].w;
        }
        __syncthreads();

        if (kt + 16 < K) {
#pragma unroll
            for (int i = 0; i < 2; i++) {
                int r = lr + i * 64;
                na[i] = *(const float4*)(Ab + (size_t)r * K + kt + 16 + lc);
                nb[i] = *(const float4*)(Bb + (size_t)r * K + kt + 16 + lc);
            }
        }

#pragma unroll
        for (int kk = 0; kk < 16; kk++) {
            float af[8], bf[8];
            *(float4*)&af[0] = *(const float4*)&As[kk][trow * 8];
            *(float4*)&af[4] = *(const float4*)&As[kk][trow * 8 + 4];
            *(float4*)&bf[0] = *(const float4*)&Bs[kk][tcol * 8];
            *(float4*)&bf[4] = *(const float4*)&Bs[kk][tcol * 8 + 4];
#pragma unroll
            for (int i = 0; i < 8; i++)
#pragma unroll
                for (int j = 0; j < 8; j++)
                    acc[i][j] += af[i] * bf[j];
        }
        __syncthreads();
    }

    float* Cb = C + (size_t)(blockIdx.y * 128 + trow * 8) * N +
                blockIdx.x * 128 + tcol * 8;
#pragma unroll
    for (int i = 0; i < 8; i++) {
        *(float4*)(Cb + (size_t)i * N) =
            make_float4(acc[i][0], acc[i][1], acc[i][2], acc[i][3]);
        *(float4*)(Cb + (size_t)i * N + 4) =
            make_float4(acc[i][4], acc[i][5], acc[i][6], acc[i][7]);
    }
}

// a = silu(a) * b   (in place; float4 vectorized)
__global__ void silu_mul_kernel(float* __restrict__ a,
                                const float* __restrict__ b, int n4) {
    int i = blockIdx.x * blockDim.x + threadIdx.x;
    if (i >= n4) return;
    float4 va = ((const float4*)a)[i];
    float4 vb = ((const float4*)b)[i];
    va.x = (va.x / (1.0f + __expf(-va.x))) * vb.x;
    va.y = (va.y / (1.0f + __expf(-va.y))) * vb.y;
    va.z = (va.z / (1.0f + __expf(-va.z))) * vb.z;
    va.w = (va.w / (1.0f + __expf(-va.w))) * vb.w;
    ((float4*)a)[i] = va;
}

extern "C" void kernel_launch(void* const* d_in, const int* in_sizes, int n_in,
                              void* d_out, int out_size) {
    const float* x      = (const float*)d_in[0];
    const void*  w1_idx = d_in[1];
    const void*  w1_qs  = d_in[2];
    const float* w1_qf  = (const float*)d_in[3];
    const float* w1_m   = (const float*)d_in[4];
    const void*  w2_idx = d_in[5];
    const void*  w2_qs  = d_in[6];
    const float* w2_qf  = (const float*)d_in[7];
    const float* w2_m   = (const float*)d_in[8];
    const void*  w3_idx = d_in[9];
    const void*  w3_qs  = d_in[10];
    const float* w3_qf  = (const float*)d_in[11];
    const float* w3_m   = (const float*)d_in[12];

    float *w1, *w2, *w3, *a, *b;
    cudaGetSymbolAddress((void**)&w1, g_w1);
    cudaGetSymbolAddress((void**)&w2, g_w2);
    cudaGetSymbolAddress((void**)&w3, g_w3);
    cudaGetSymbolAddress((void**)&a,  g_a);
    cudaGetSymbolAddress((void**)&b,  g_b);

    detect_types<<<1, 1>>>((const uint8_t*)w1_idx, (const uint8_t*)w1_qs);

    const int n4w = (HH * DD) / 4;  // same element count for all three weights
    dequant_kernel<<<(n4w + 255) / 256, 256>>>(w1_idx, w1_qs, w1_qf, w1_m, w1, n4w);
    dequant_kernel<<<(n4w + 255) / 256, 256>>>(w2_idx, w2_qs, w2_qf, w2_m, w2, n4w);
    dequant_kernel<<<(n4w + 255) / 256, 256>>>(w3_idx, w3_qs, w3_qf, w3_m, w3, n4w);

    dim3 g1(HH / 128, TT / 128);  // 86 x 16
    sgemm_nt<<<g1, 256>>>(x, w1, a, TT, HH, DD);
    sgemm_nt<<<g1, 256>>>(x, w2, b, TT, HH, DD);

    const int n4h = (TT * HH) / 4;
    silu_mul_kernel<<<(n4h + 255) / 256, 256>>>(a, b, n4h);

    dim3 g3(DD / 128, TT / 128);  // 32 x 16
    sgemm_nt<<<g3, 256>>>(a, w3, (float*)d_out, TT, DD, HH);
}

// round 4
// speedup vs baseline: 1.0005x; 1.0005x over previous
#include <cuda_runtime.h>
#include <cstdint>

// NF4 MLP: out = (silu(x@w1^T) * (x@w2^T)) @ w3^T
// w1,w2,w3 NF4-dequantized (blockwise absmax + double-quantized scalers).
#define DD 4096
#define HH 11008
#define TT 2048

__constant__ float c_nf4[16] = {
    -1.0f, -0.6961928009986877f, -0.5250730514526367f, -0.39491748809814453f,
    -0.28444138169288635f, -0.18477343022823334f, -0.09105003625154495f, 0.0f,
    0.07958029955625534f, 0.16093020141124725f, 0.24611230194568634f,
    0.33791524171829224f, 0.44070982933044434f, 0.5626170039176941f,
    0.7229568362236023f, 1.0f};

// Static scratch (device allocation is banned; __device__ globals are the
// sanctioned workaround). ~720 MB total.
__device__ float g_w1[(size_t)HH * DD];
__device__ float g_w2[(size_t)HH * DD];
__device__ float g_w3[(size_t)DD * HH];
__device__ float g_a[(size_t)TT * HH];   // silu input, then reused as h
__device__ float g_b[(size_t)TT * HH];

// dtype flags for (idx, qs) inputs: 0 = int8, 1 = int32 (widened), 2 = float32
__device__ int g_flags[2];

// ---------------------------------------------------------------------------
// Probe the raw byte pattern of idx / qs buffers to discover how the harness
// uploaded the reference's int8 arrays. idx codes are 0..15; qs are -127..127.
//   int32 widening: idx -> bytes 1..3 all zero; qs -> bytes 1..3 = sign ext.
//   float32      : low mantissa bytes (0..1) all zero for small integers.
//   int8 (native): byte stream of values; none of the above patterns hold.
// ---------------------------------------------------------------------------
__global__ void detect_types(const uint8_t* __restrict__ idx,
                             const uint8_t* __restrict__ qs) {
    if (threadIdx.x | blockIdx.x) return;
    // --- idx ---
    int nz0 = 0, nz1 = 0, nz23 = 0;
    for (int i = 0; i < 256; i++) {
        nz0  += (idx[i * 4 + 0] != 0);
        nz1  += (idx[i * 4 + 1] != 0);
        nz23 += (idx[i * 4 + 2] != 0) + (idx[i * 4 + 3] != 0);
    }
    int im;
    if (nz1 == 0 && nz23 == 0) im = 1;          // int32
    else if (nz0 == 0 && nz1 == 0) im = 2;      // float32
    else im = 0;                                 // int8
    g_flags[0] = im;

    // --- qs ---
    bool i32ok = true, f32ok = true;
    for (int i = 0; i < 256; i++) {
        uint8_t b0 = qs[i * 4], b1 = qs[i * 4 + 1],
                b2 = qs[i * 4 + 2], b3 = qs[i * 4 + 3];
        uint8_t ext = (b0 & 0x80) ? 0xFF : 0x00;
        if (!(b1 == ext && b2 == ext && b3 == ext)) i32ok = false;
        if (b0 != 0 || b1 != 0) f32ok = false;
    }
    g_flags[1] = i32ok ? 1 : (f32ok ? 2 : 0);
}

// ---------------------------------------------------------------------------
// Dequant: w[i] = NF4[idx[i]] * (qs[i/64]/qf[i/16384] + m)
// 4 elements/thread; 4 elems always share one 64-elem block.
// ---------------------------------------------------------------------------
__global__ void dequant_kernel(const void* __restrict__ idxv,
                               const void* __restrict__ qsv,
                               const float* __restrict__ qf,
                               const float* __restrict__ mp,
                               float* __restrict__ out, int n4) {
    int i = blockIdx.x * blockDim.x + threadIdx.x;
    if (i >= n4) return;
    const float m = *mp;
    const int im = g_flags[0], qm = g_flags[1];
    int blk = i >> 4;  // (i*4) >> 6 : 64-elem nf4 block index

    float q;
    if (qm == 1)      q = (float)((const int*)qsv)[blk];
    else if (qm == 2) q = ((const float*)qsv)[blk];
    else              q = (float)((const int8_t*)qsv)[blk];
    float scal = q / qf[blk >> 8] + m;

    int c0, c1, c2, c3;
    if (im == 1) {
        int4 w = ((const int4*)idxv)[i];
        c0 = w.x; c1 = w.y; c2 = w.z; c3 = w.w;
    } else if (im == 2) {
        float4 w = ((const float4*)idxv)[i];
        c0 = (int)w.x; c1 = (int)w.y; c2 = (int)w.z; c3 = (int)w.w;
    } else {
        char4 c = ((const char4*)idxv)[i];
        c0 = c.x; c1 = c.y; c2 = c.z; c3 = c.w;
    }
    float4 o;
    o.x = c_nf4[c0 & 15] * scal;
    o.y = c_nf4[c1 & 15] * scal;
    o.z = c_nf4[c2 & 15] * scal;
    o.w = c_nf4[c3 & 15] * scal;
    ((float4*)out)[i] = o;
}

// ---------------------------------------------------------------------------
// fp32 NT SGEMM: C[M,N] = A[M,K] (row-major) * B[N,K]^T (row-major)
// 128x128 block tile, BK=16, 256 threads, 8x8 register tile per thread,
// register-prefetch pipelining. M,N % 128 == 0, K % 16 == 0.
// ---------------------------------------------------------------------------
__global__ __launch_bounds__(256, 2) void sgemm_nt(const float* __restrict__ A,
                                                   const float* __restrict__ B,
                                                   float* __restrict__ C,
                                                   int M, int N, int K) {
    __shared__ float As[16][128];
    __shared__ float Bs[16][128];

    const int tid  = threadIdx.x;
    const int trow = tid >> 4;   // 0..15 (M dir)
    const int tcol = tid & 15;   // 0..15 (N dir)

    const float* Ab = A + (size_t)(blockIdx.y * 128) * K;
    const float* Bb = B + (size_t)(blockIdx.x * 128) * K;

    const int lr = tid >> 2;        // 0..63
    const int lc = (tid & 3) << 2;  // 0,4,8,12

    float acc[8][8] = {};
    float4 na[2], nb[2];

#pragma unroll
    for (int i = 0; i < 2; i++) {
        int r = lr + i * 64;
        na[i] = *(const float4*)(Ab + (size_t)r * K + lc);
        nb[i] = *(const float4*)(Bb + (size_t)r * K + lc);
    }

    for (int kt = 0; kt < K; kt += 16) {
#pragma unroll
        for (int i = 0; i < 2; i++) {
            int r = lr + i * 64;
            As[lc + 0][r] = na[i].x; As[lc + 1][r] = na[i].y;
            As[lc + 2][r] = na[i].z; As[lc + 3][r] = na[i].w;
            Bs[lc + 0][r] = nb[i].x; Bs[lc + 1][r] = nb[i].y;
            Bs[lc + 2][r] = nb[i].z; Bs[lc + 3][r] = nb[i].w;
        }
        __syncthreads();

        if (kt + 16 < K) {
#pragma unroll
            for (int i = 0; i < 2; i++) {
                int r = lr + i * 64;
                na[i] = *(const float4*)(Ab + (size_t)r * K + kt + 16 + lc);
                nb[i] = *(const float4*)(Bb + (size_t)r * K + kt + 16 + lc);
            }
        }

#pragma unroll
        for (int kk = 0; kk < 16; kk++) {
            float af[8], bf[8];
            *(float4*)&af[0] = *(const float4*)&As[kk][trow * 8];
            *(float4*)&af[4] = *(const float4*)&As[kk][trow * 8 + 4];
            *(float4*)&bf[0] = *(const float4*)&Bs[kk][tcol * 8];
            *(float4*)&bf[4] = *(const float4*)&Bs[kk][tcol * 8 + 4];
#pragma unroll
            for (int i = 0; i < 8; i++)
#pragma unroll
                for (int j = 0; j < 8; j++)
                    acc[i][j] += af[i] * bf[j];
        }
        __syncthreads();
    }

    float* Cb = C + (size_t)(blockIdx.y * 128 + trow * 8) * N +
                blockIdx.x * 128 + tcol * 8;
#pragma unroll
    for (int i = 0; i < 8; i++) {
        *(float4*)(Cb + (size_t)i * N) =
            make_float4(acc[i][0], acc[i][1], acc[i][2], acc[i][3]);
        *(float4*)(Cb + (size_t)i * N + 4) =
            make_float4(acc[i][4], acc[i][5], acc[i][6], acc[i][7]);
    }
}

// a = silu(a) * b   (in place; float4 vectorized)
__global__ void silu_mul_kernel(float* __restrict__ a,
                                const float* __restrict__ b, int n4) {
    int i = blockIdx.x * blockDim.x + threadIdx.x;
    if (i >= n4) return;
    float4 va = ((const float4*)a)[i];
    float4 vb = ((const float4*)b)[i];
    va.x = (va.x / (1.0f + __expf(-va.x))) * vb.x;
    va.y = (va.y / (1.0f + __expf(-va.y))) * vb.y;
    va.z = (va.z / (1.0f + __expf(-va.z))) * vb.z;
    va.w = (va.w / (1.0f + __expf(-va.w))) * vb.w;
    ((float4*)a)[i] = va;
}

extern "C" void kernel_launch(void* const* d_in, const int* in_sizes, int n_in,
                              void* d_out, int out_size) {
    const float* x      = (const float*)d_in[0];
    const void*  w1_idx = d_in[1];
    const void*  w1_qs  = d_in[2];
    const float* w1_qf  = (const float*)d_in[3];
    const float* w1_m   = (const float*)d_in[4];
    const void*  w2_idx = d_in[5];
    const void*  w2_qs  = d_in[6];
    const float* w2_qf  = (const float*)d_in[7];
    const float* w2_m   = (const float*)d_in[8];
    const void*  w3_idx = d_in[9];
    const void*  w3_qs  = d_in[10];
    const float* w3_qf  = (const float*)d_in[11];
    const float* w3_m   = (const float*)d_in[12];

    float *w1, *w2, *w3, *a, *b;
    cudaGetSymbolAddress((void**)&w1, g_w1);
    cudaGetSymbolAddress((void**)&w2, g_w2);
    cudaGetSymbolAddress((void**)&w3, g_w3);
    cudaGetSymbolAddress((void**)&a,  g_a);
    cudaGetSymbolAddress((void**)&b,  g_b);

    detect_types<<<1, 1>>>((const uint8_t*)w1_idx, (const uint8_t*)w1_qs);

    const int n4w = (HH * DD) / 4;  // same element count for all three weights
    dequant_kernel<<<(n4w + 255) / 256, 256>>>(w1_idx, w1_qs, w1_qf, w1_m, w1, n4w);
    dequant_kernel<<<(n4w + 255) / 256, 256>>>(w2_idx, w2_qs, w2_qf, w2_m, w2, n4w);
    dequant_kernel<<<(n4w + 255) / 256, 256>>>(w3_idx, w3_qs, w3_qf, w3_m, w3, n4w);

    dim3 g1(HH / 128, TT / 128);  // 86 x 16
    sgemm_nt<<<g1, 256>>>(x, w1, a, TT, HH, DD);
    sgemm_nt<<<g1, 256>>>(x, w2, b, TT, HH, DD);

    const int n4h = (TT * HH) / 4;
    silu_mul_kernel<<<(n4h + 255) / 256, 256>>>(a, b, n4h);

    dim3 g3(DD / 128, TT / 128);  // 32 x 16
    sgemm_nt<<<g3, 256>>>(a, w3, (float*)d_out, TT, DD, HH);
}